// round 1
// baseline (speedup 1.0000x reference)
#include <cuda_runtime.h>
#include <math.h>

// Problem constants (match reference)
#define NU 100000
#define NI 50000
#define D  64

// Scratch: __device__ globals (allocation is forbidden).
// u/i ping-pong + sums, social ping-pong + sum. ~192 MB total.
__device__ float g_uA[NU * D];
__device__ float g_uB[NU * D];
__device__ float g_uS[NU * D];
__device__ float g_iA[NI * D];
__device__ float g_iB[NI * D];
__device__ float g_iS[NI * D];
__device__ float g_sA[NU * D];
__device__ float g_sB[NU * D];
__device__ float g_sS[NU * D];

__device__ __forceinline__ void red2(float* p, float a, float b) {
    asm volatile("red.global.add.v2.f32 [%0], {%1, %2};"
                 :: "l"(p), "f"(a), "f"(b) : "memory");
}

// Initialize: u_cur=u_sum=user_emb ; i_cur=i_sum=item_emb ; s_cur=s_sum=user_emb
__global__ void init_kernel(const float* __restrict__ ue, const float* __restrict__ ie) {
    const int tid = blockIdx.x * blockDim.x + threadIdx.x;
    const int stride = gridDim.x * blockDim.x;
    const int nu4 = NU * D / 4;
    const int ni4 = NI * D / 4;
    const float4* u4 = (const float4*)ue;
    const float4* i4 = (const float4*)ie;
    for (int i = tid; i < nu4; i += stride) {
        float4 v = u4[i];
        ((float4*)g_uA)[i] = v;
        ((float4*)g_uS)[i] = v;
        ((float4*)g_sA)[i] = v;
        ((float4*)g_sS)[i] = v;
    }
    for (int i = tid; i < ni4; i += stride) {
        float4 v = i4[i];
        ((float4*)g_iA)[i] = v;
        ((float4*)g_iS)[i] = v;
    }
}

// Zero two buffers (b may be null)
__global__ void zero2_kernel(float4* __restrict__ a, int na4,
                             float4* __restrict__ b, int nb4) {
    const int tid = blockIdx.x * blockDim.x + threadIdx.x;
    const int stride = gridDim.x * blockDim.x;
    const float4 z = make_float4(0.f, 0.f, 0.f, 0.f);
    for (int i = tid; i < na4; i += stride) a[i] = z;
    for (int i = tid; i < nb4; i += stride) b[i] = z;
}

// sum += nxt
__global__ void accum_kernel(float4* __restrict__ sum, const float4* __restrict__ nxt, int n4) {
    const int tid = blockIdx.x * blockDim.x + threadIdx.x;
    const int stride = gridDim.x * blockDim.x;
    for (int i = tid; i < n4; i += stride) {
        float4 s = sum[i];
        float4 v = nxt[i];
        s.x += v.x; s.y += v.y; s.z += v.z; s.w += v.w;
        sum[i] = s;
    }
}

// Fused bipartite SpMM: for each R edge e (r,c,v):
//   u_next[r] += v * i_cur[c]
//   i_next[c] += v * u_cur[r]
// One warp per edge; lane handles 2 dims (float2).
__global__ void spmm_bip_kernel(const int* __restrict__ rows, const int* __restrict__ cols,
                                const float* __restrict__ vals, int nnz,
                                const float* __restrict__ u_cur, const float* __restrict__ i_cur,
                                float* __restrict__ u_next, float* __restrict__ i_next) {
    const int gw = (blockIdx.x * blockDim.x + threadIdx.x) >> 5;
    const int lane = threadIdx.x & 31;
    if (gw >= nnz) return;
    const int r = rows[gw];
    const int c = cols[gw];
    const float v = vals[gw];
    const size_t ro = (size_t)r * D + lane * 2;
    const size_t co = (size_t)c * D + lane * 2;
    const float2 iv = *(const float2*)(i_cur + co);
    const float2 uv = *(const float2*)(u_cur + ro);
    red2(u_next + ro, v * iv.x, v * iv.y);
    red2(i_next + co, v * uv.x, v * uv.y);
}

// Social SpMM: s_next[r] += v * s_cur[c]
__global__ void spmm_soc_kernel(const int* __restrict__ rows, const int* __restrict__ cols,
                                const float* __restrict__ vals, int nnz,
                                const float* __restrict__ s_cur, float* __restrict__ s_next) {
    const int gw = (blockIdx.x * blockDim.x + threadIdx.x) >> 5;
    const int lane = threadIdx.x & 31;
    if (gw >= nnz) return;
    const int r = rows[gw];
    const int c = cols[gw];
    const float v = vals[gw];
    const float2 sv = *(const float2*)(s_cur + (size_t)c * D + lane * 2);
    red2(s_next + (size_t)r * D + lane * 2, v * sv.x, v * sv.y);
}

// final_user = l2norm(0.6 * u_sum/4 + 0.4 * s_sum/3)
__global__ void final_user_kernel(float* __restrict__ out) {
    const int gw = (blockIdx.x * blockDim.x + threadIdx.x) >> 5;
    const int lane = threadIdx.x & 31;
    if (gw >= NU) return;
    const size_t off = (size_t)gw * D + lane * 2;
    const float2 u = *(const float2*)(g_uS + off);
    const float2 s = *(const float2*)(g_sS + off);
    const float cu = 0.6f / 4.0f;
    const float cs = 0.4f / 3.0f;
    float x = cu * u.x + cs * s.x;
    float y = cu * u.y + cs * s.y;
    float sq = x * x + y * y;
    #pragma unroll
    for (int o = 16; o > 0; o >>= 1) sq += __shfl_xor_sync(0xFFFFFFFFu, sq, o);
    const float inv = 1.0f / fmaxf(sqrtf(sq), 1e-12f);
    float2 r; r.x = x * inv; r.y = y * inv;
    *(float2*)(out + off) = r;
}

// final_item = l2norm(i_sum/4)
__global__ void final_item_kernel(float* __restrict__ out) {
    const int gw = (blockIdx.x * blockDim.x + threadIdx.x) >> 5;
    const int lane = threadIdx.x & 31;
    if (gw >= NI) return;
    const size_t off = (size_t)gw * D + lane * 2;
    const float2 iv = *(const float2*)(g_iS + off);
    float x = 0.25f * iv.x;
    float y = 0.25f * iv.y;
    float sq = x * x + y * y;
    #pragma unroll
    for (int o = 16; o > 0; o >>= 1) sq += __shfl_xor_sync(0xFFFFFFFFu, sq, o);
    const float inv = 1.0f / fmaxf(sqrtf(sq), 1e-12f);
    float2 r; r.x = x * inv; r.y = y * inv;
    *(float2*)(out + off) = r;
}

extern "C" void kernel_launch(void* const* d_in, const int* in_sizes, int n_in,
                              void* d_out, int out_size) {
    const float* ue = (const float*)d_in[0];   // user_emb [NU, D]
    const float* ie = (const float*)d_in[1];   // item_emb [NI, D]
    const float* rv = (const float*)d_in[2];   // r_vals
    const float* sv = (const float*)d_in[3];   // s_vals
    const int*   rr = (const int*)d_in[4];     // r_rows
    const int*   rc = (const int*)d_in[5];     // r_cols
    const int*   sr = (const int*)d_in[6];     // s_rows
    const int*   sc = (const int*)d_in[7];     // s_cols
    const int nnzR = in_sizes[2];
    const int nnzS = in_sizes[3];
    float* out = (float*)d_out;

    float *uA, *uB, *uS, *iA, *iB, *iS, *sA, *sB, *sS;
    cudaGetSymbolAddress((void**)&uA, g_uA);
    cudaGetSymbolAddress((void**)&uB, g_uB);
    cudaGetSymbolAddress((void**)&uS, g_uS);
    cudaGetSymbolAddress((void**)&iA, g_iA);
    cudaGetSymbolAddress((void**)&iB, g_iB);
    cudaGetSymbolAddress((void**)&iS, g_iS);
    cudaGetSymbolAddress((void**)&sA, g_sA);
    cudaGetSymbolAddress((void**)&sB, g_sB);
    cudaGetSymbolAddress((void**)&sS, g_sS);

    const int nu4 = NU * D / 4;
    const int ni4 = NI * D / 4;
    const int ZB = 1024, ZT = 256;

    init_kernel<<<ZB, ZT>>>(ue, ie);

    // Bipartite propagation: 3 layers, ping-pong A<->B
    float* uc = uA; float* un = uB;
    float* ic = iA; float* inx = iB;
    for (int l = 0; l < 3; l++) {
        zero2_kernel<<<ZB, ZT>>>((float4*)un, nu4, (float4*)inx, ni4);
        const int blocks = (nnzR + 7) / 8;  // 8 warps per 256-thread block
        spmm_bip_kernel<<<blocks, 256>>>(rr, rc, rv, nnzR, uc, ic, un, inx);
        accum_kernel<<<ZB, ZT>>>((float4*)uS, (const float4*)un, nu4);
        accum_kernel<<<ZB, ZT>>>((float4*)iS, (const float4*)inx, ni4);
        { float* t = uc; uc = un; un = t; }
        { float* t = ic; ic = inx; inx = t; }
    }

    // Social propagation: 2 layers
    float* scur = sA; float* snxt = sB;
    for (int l = 0; l < 2; l++) {
        zero2_kernel<<<ZB, ZT>>>((float4*)snxt, nu4, (float4*)snxt, 0);
        const int blocks = (nnzS + 7) / 8;
        spmm_soc_kernel<<<blocks, 256>>>(sr, sc, sv, nnzS, scur, snxt);
        accum_kernel<<<ZB, ZT>>>((float4*)sS, (const float4*)snxt, nu4);
        { float* t = scur; scur = snxt; snxt = t; }
    }

    // Epilogue: normalize + write out (user rows first, then item rows)
    final_user_kernel<<<(NU * 32 + 255) / 256, 256>>>(out);
    final_item_kernel<<<(NI * 32 + 255) / 256, 256>>>(out + (size_t)NU * D);
}

// round 2
// speedup vs baseline: 1.9286x; 1.9286x over previous
#include <cuda_runtime.h>
#include <math.h>

#define NU 100000
#define NI 50000
#define D  64
#define MAXR 3200000
#define MAXS 2000000
#define SCAN_BLK 1024
#define MAXPART 128   // ceil(100000/1024) = 98 <= 128

// ---- scratch (__device__ globals; allocation is forbidden) ----
__device__ float g_uA[NU * D];
__device__ float g_uB[NU * D];
__device__ float g_uS[NU * D];
__device__ float g_iA[NI * D];
__device__ float g_iB[NI * D];
__device__ float g_iS[NI * D];
__device__ float g_sA[NU * D];
__device__ float g_sB[NU * D];
__device__ float g_sS[NU * D];

__device__ int g_degU[NU], g_offU[NU], g_curU[NU];
__device__ int g_degI[NI], g_offI[NI], g_curI[NI];
__device__ int g_degS[NU], g_offS[NU], g_curS[NU];
__device__ int g_partU[MAXPART], g_partI[MAXPART], g_partS[MAXPART];

__device__ int2 g_uPair[MAXR];  // (col, val)  sorted by r_row
__device__ int2 g_iPair[MAXR];  // (row, val)  sorted by r_col
__device__ int2 g_sPair[MAXS];  // (col, val)  sorted by s_row

// -------------------- init --------------------
__global__ void init_kernel(const float* __restrict__ ue, const float* __restrict__ ie) {
    const int tid = blockIdx.x * blockDim.x + threadIdx.x;
    const int stride = gridDim.x * blockDim.x;
    const int nu4 = NU * D / 4;
    const int ni4 = NI * D / 4;
    const float4* u4 = (const float4*)ue;
    const float4* i4 = (const float4*)ie;
    for (int i = tid; i < nu4; i += stride) {
        float4 v = u4[i];
        ((float4*)g_uA)[i] = v;
        ((float4*)g_uS)[i] = v;
        ((float4*)g_sA)[i] = v;
        ((float4*)g_sS)[i] = v;
    }
    for (int i = tid; i < ni4; i += stride) {
        float4 v = i4[i];
        ((float4*)g_iA)[i] = v;
        ((float4*)g_iS)[i] = v;
    }
}

// zero all int bookkeeping arrays
__global__ void zero_ints_kernel() {
    const int tid = blockIdx.x * blockDim.x + threadIdx.x;
    const int stride = gridDim.x * blockDim.x;
    for (int i = tid; i < NU; i += stride) {
        g_degU[i] = 0; g_curU[i] = 0;
        g_degS[i] = 0; g_curS[i] = 0;
    }
    for (int i = tid; i < NI; i += stride) {
        g_degI[i] = 0; g_curI[i] = 0;
    }
}

// -------------------- histograms --------------------
__global__ void hist_r_kernel(const int* __restrict__ rr, const int* __restrict__ rc, int nnz) {
    const int tid = blockIdx.x * blockDim.x + threadIdx.x;
    const int stride = gridDim.x * blockDim.x;
    for (int e = tid; e < nnz; e += stride) {
        atomicAdd(&g_degU[rr[e]], 1);
        atomicAdd(&g_degI[rc[e]], 1);
    }
}
__global__ void hist_s_kernel(const int* __restrict__ sr, int nnz) {
    const int tid = blockIdx.x * blockDim.x + threadIdx.x;
    const int stride = gridDim.x * blockDim.x;
    for (int e = tid; e < nnz; e += stride) {
        atomicAdd(&g_degS[sr[e]], 1);
    }
}

// -------------------- exclusive scan (3 phases) --------------------
__global__ void scanA_kernel(const int* __restrict__ deg, int* __restrict__ off,
                             int* __restrict__ part, int n) {
    __shared__ int sm[SCAN_BLK];
    const int t = threadIdx.x;
    const int base = blockIdx.x * SCAN_BLK;
    int v = (base + t < n) ? deg[base + t] : 0;
    sm[t] = v; __syncthreads();
    for (int o = 1; o < SCAN_BLK; o <<= 1) {
        int x = (t >= o) ? sm[t - o] : 0;
        __syncthreads();
        sm[t] += x;
        __syncthreads();
    }
    if (base + t < n) off[base + t] = sm[t] - v;   // exclusive
    if (t == SCAN_BLK - 1) part[blockIdx.x] = sm[t];
}
__global__ void scanB_kernel(int* __restrict__ part, int nb) {
    __shared__ int sm[MAXPART];
    const int t = threadIdx.x;
    int v = (t < nb) ? part[t] : 0;
    sm[t] = v; __syncthreads();
    for (int o = 1; o < MAXPART; o <<= 1) {
        int x = (t >= o) ? sm[t - o] : 0;
        __syncthreads();
        sm[t] += x;
        __syncthreads();
    }
    if (t < nb) part[t] = sm[t] - v;               // exclusive
}
__global__ void scanC_kernel(int* __restrict__ off, const int* __restrict__ part, int n) {
    const int i = blockIdx.x * blockDim.x + threadIdx.x;
    if (i < n) off[i] += part[i >> 10];            // SCAN_BLK = 1024
}

// -------------------- scatter (counting-sort placement) --------------------
__global__ void scatter_r_kernel(const int* __restrict__ rr, const int* __restrict__ rc,
                                 const float* __restrict__ rv, int nnz) {
    const int tid = blockIdx.x * blockDim.x + threadIdx.x;
    const int stride = gridDim.x * blockDim.x;
    for (int e = tid; e < nnz; e += stride) {
        const int r = rr[e];
        const int c = rc[e];
        const int vb = __float_as_int(rv[e]);
        const int pu = g_offU[r] + atomicAdd(&g_curU[r], 1);
        g_uPair[pu] = make_int2(c, vb);
        const int pi = g_offI[c] + atomicAdd(&g_curI[c], 1);
        g_iPair[pi] = make_int2(r, vb);
    }
}
__global__ void scatter_s_kernel(const int* __restrict__ sr, const int* __restrict__ sc,
                                 const float* __restrict__ sv, int nnz) {
    const int tid = blockIdx.x * blockDim.x + threadIdx.x;
    const int stride = gridDim.x * blockDim.x;
    for (int e = tid; e < nnz; e += stride) {
        const int p = g_offS[sr[e]] + atomicAdd(&g_curS[sr[e]], 1);
        g_sPair[p] = make_int2(sc[e], __float_as_int(sv[e]));
    }
}

// -------------------- CSR row-gather SpMM (warp per row) --------------------
// Computes acc = sum_j v_j * x[col_j] for this row; each lane owns 2 dims.
__device__ __forceinline__ void row_gather(const int2* __restrict__ pairs,
                                           int beg, int d, int lane,
                                           const float* __restrict__ x,
                                           float& outx, float& outy) {
    float ax = 0.f, ay = 0.f, bx = 0.f, by = 0.f;
    int j = beg;
    const int end = beg + d;
    for (; j + 1 < end; j += 2) {
        const int2 p0 = __ldg(&pairs[j]);
        const int2 p1 = __ldg(&pairs[j + 1]);
        const float2 x0 = *(const float2*)(x + (size_t)p0.x * D + lane * 2);
        const float2 x1 = *(const float2*)(x + (size_t)p1.x * D + lane * 2);
        const float v0 = __int_as_float(p0.y);
        const float v1 = __int_as_float(p1.y);
        ax = fmaf(v0, x0.x, ax); ay = fmaf(v0, x0.y, ay);
        bx = fmaf(v1, x1.x, bx); by = fmaf(v1, x1.y, by);
    }
    if (j < end) {
        const int2 p = __ldg(&pairs[j]);
        const float2 xv = *(const float2*)(x + (size_t)p.x * D + lane * 2);
        const float v = __int_as_float(p.y);
        ax = fmaf(v, xv.x, ax); ay = fmaf(v, xv.y, ay);
    }
    outx = ax + bx;
    outy = ay + by;
}

// Fused bipartite layer: warps [0, NU) do u_next = R @ i_cur; warps [NU, NU+NI)
// do i_next = R^T @ u_cur. Also folds sum += next (no separate zero/accum pass).
__global__ void layer_bip_kernel(const float* __restrict__ u_cur, const float* __restrict__ i_cur,
                                 float* __restrict__ u_next, float* __restrict__ i_next) {
    const int w = (blockIdx.x * blockDim.x + threadIdx.x) >> 5;
    const int lane = threadIdx.x & 31;
    if (w < NU) {
        float x, y;
        row_gather(g_uPair, g_offU[w], g_degU[w], lane, i_cur, x, y);
        const size_t off = (size_t)w * D + lane * 2;
        float2 r; r.x = x; r.y = y;
        *(float2*)(u_next + off) = r;
        float2 s = *(const float2*)(g_uS + off);
        s.x += x; s.y += y;
        *(float2*)(g_uS + off) = s;
    } else if (w < NU + NI) {
        const int row = w - NU;
        float x, y;
        row_gather(g_iPair, g_offI[row], g_degI[row], lane, u_cur, x, y);
        const size_t off = (size_t)row * D + lane * 2;
        float2 r; r.x = x; r.y = y;
        *(float2*)(i_next + off) = r;
        float2 s = *(const float2*)(g_iS + off);
        s.x += x; s.y += y;
        *(float2*)(g_iS + off) = s;
    }
}

__global__ void layer_soc_kernel(const float* __restrict__ s_cur, float* __restrict__ s_next) {
    const int w = (blockIdx.x * blockDim.x + threadIdx.x) >> 5;
    const int lane = threadIdx.x & 31;
    if (w >= NU) return;
    float x, y;
    row_gather(g_sPair, g_offS[w], g_degS[w], lane, s_cur, x, y);
    const size_t off = (size_t)w * D + lane * 2;
    float2 r; r.x = x; r.y = y;
    *(float2*)(s_next + off) = r;
    float2 s = *(const float2*)(g_sS + off);
    s.x += x; s.y += y;
    *(float2*)(g_sS + off) = s;
}

// -------------------- epilogue --------------------
__global__ void final_user_kernel(float* __restrict__ out) {
    const int gw = (blockIdx.x * blockDim.x + threadIdx.x) >> 5;
    const int lane = threadIdx.x & 31;
    if (gw >= NU) return;
    const size_t off = (size_t)gw * D + lane * 2;
    const float2 u = *(const float2*)(g_uS + off);
    const float2 s = *(const float2*)(g_sS + off);
    const float cu = 0.6f / 4.0f;
    const float cs = 0.4f / 3.0f;
    float x = cu * u.x + cs * s.x;
    float y = cu * u.y + cs * s.y;
    float sq = x * x + y * y;
    #pragma unroll
    for (int o = 16; o > 0; o >>= 1) sq += __shfl_xor_sync(0xFFFFFFFFu, sq, o);
    const float inv = 1.0f / fmaxf(sqrtf(sq), 1e-12f);
    float2 r; r.x = x * inv; r.y = y * inv;
    *(float2*)(out + off) = r;
}
__global__ void final_item_kernel(float* __restrict__ out) {
    const int gw = (blockIdx.x * blockDim.x + threadIdx.x) >> 5;
    const int lane = threadIdx.x & 31;
    if (gw >= NI) return;
    const size_t off = (size_t)gw * D + lane * 2;
    const float2 iv = *(const float2*)(g_iS + off);
    float x = 0.25f * iv.x;
    float y = 0.25f * iv.y;
    float sq = x * x + y * y;
    #pragma unroll
    for (int o = 16; o > 0; o >>= 1) sq += __shfl_xor_sync(0xFFFFFFFFu, sq, o);
    const float inv = 1.0f / fmaxf(sqrtf(sq), 1e-12f);
    float2 r; r.x = x * inv; r.y = y * inv;
    *(float2*)(out + off) = r;
}

extern "C" void kernel_launch(void* const* d_in, const int* in_sizes, int n_in,
                              void* d_out, int out_size) {
    const float* ue = (const float*)d_in[0];
    const float* ie = (const float*)d_in[1];
    const float* rv = (const float*)d_in[2];
    const float* sv = (const float*)d_in[3];
    const int*   rr = (const int*)d_in[4];
    const int*   rc = (const int*)d_in[5];
    const int*   sr = (const int*)d_in[6];
    const int*   sc = (const int*)d_in[7];
    const int nnzR = in_sizes[2];
    const int nnzS = in_sizes[3];
    float* out = (float*)d_out;

    float *uA, *uB, *iA, *iB, *sA, *sB;
    cudaGetSymbolAddress((void**)&uA, g_uA);
    cudaGetSymbolAddress((void**)&uB, g_uB);
    cudaGetSymbolAddress((void**)&iA, g_iA);
    cudaGetSymbolAddress((void**)&iB, g_iB);
    cudaGetSymbolAddress((void**)&sA, g_sA);
    cudaGetSymbolAddress((void**)&sB, g_sB);

    int *degU, *offU, *partU, *degI, *offI, *partI, *degS, *offS, *partS;
    cudaGetSymbolAddress((void**)&degU, g_degU);
    cudaGetSymbolAddress((void**)&offU, g_offU);
    cudaGetSymbolAddress((void**)&partU, g_partU);
    cudaGetSymbolAddress((void**)&degI, g_degI);
    cudaGetSymbolAddress((void**)&offI, g_offI);
    cudaGetSymbolAddress((void**)&partI, g_partI);
    cudaGetSymbolAddress((void**)&degS, g_degS);
    cudaGetSymbolAddress((void**)&offS, g_offS);
    cudaGetSymbolAddress((void**)&partS, g_partS);

    const int nbU = (NU + SCAN_BLK - 1) / SCAN_BLK;  // 98
    const int nbI = (NI + SCAN_BLK - 1) / SCAN_BLK;  // 49
    const int EB = 512;  // blocks for edge-parallel kernels
    const int ET = 256;

    // ---- build CSR (counting sort by destination) ----
    zero_ints_kernel<<<256, 256>>>();
    hist_r_kernel<<<EB, ET>>>(rr, rc, nnzR);
    hist_s_kernel<<<EB, ET>>>(sr, nnzS);

    scanA_kernel<<<nbU, SCAN_BLK>>>(degU, offU, partU, NU);
    scanB_kernel<<<1, MAXPART>>>(partU, nbU);
    scanC_kernel<<<(NU + 255) / 256, 256>>>(offU, partU, NU);

    scanA_kernel<<<nbI, SCAN_BLK>>>(degI, offI, partI, NI);
    scanB_kernel<<<1, MAXPART>>>(partI, nbI);
    scanC_kernel<<<(NI + 255) / 256, 256>>>(offI, partI, NI);

    scanA_kernel<<<nbU, SCAN_BLK>>>(degS, offS, partS, NU);
    scanB_kernel<<<1, MAXPART>>>(partS, nbU);
    scanC_kernel<<<(NU + 255) / 256, 256>>>(offS, partS, NU);

    scatter_r_kernel<<<EB, ET>>>(rr, rc, rv, nnzR);
    scatter_s_kernel<<<EB, ET>>>(sr, sc, sv, nnzS);

    // ---- embeddings init ----
    init_kernel<<<1024, 256>>>(ue, ie);

    // ---- bipartite propagation: 3 layers ----
    float* uc = uA; float* un = uB;
    float* ic = iA; float* inx = iB;
    const int bipBlocks = ((NU + NI) + 7) / 8;   // 8 warps / 256-thread block
    for (int l = 0; l < 3; l++) {
        layer_bip_kernel<<<bipBlocks, 256>>>(uc, ic, un, inx);
        { float* t = uc; uc = un; un = t; }
        { float* t = ic; ic = inx; inx = t; }
    }

    // ---- social propagation: 2 layers ----
    float* scur = sA; float* snxt = sB;
    const int socBlocks = (NU + 7) / 8;
    for (int l = 0; l < 2; l++) {
        layer_soc_kernel<<<socBlocks, 256>>>(scur, snxt);
        { float* t = scur; scur = snxt; snxt = t; }
    }

    // ---- epilogue ----
    final_user_kernel<<<(NU * 32 + 255) / 256, 256>>>(out);
    final_item_kernel<<<(NI * 32 + 255) / 256, 256>>>(out + (size_t)NU * D);
}